// round 2
// baseline (speedup 1.0000x reference)
#include <cuda_runtime.h>
#include <cuda_bf16.h>
#include <cstdint>

// ----------------------------------------------------------------------------
// VolumetricSampler: 16384 rays x 512 steps occupancy-grid sampling.
// All predicate-feeding math uses __f*_rn intrinsics to match JAX's
// separate-rounding (no FMA contraction) semantics exactly.
//
// Output layout (all float32, concatenated reference outputs):
//   origins     [8388608, 3]  -> [0,        25165824)
//   dirs        [8388608, 3]  -> [25165824, 50331648)
//   s_flat      [8388608]     -> [50331648, 58720256)
//   e_flat      [8388608]     -> [58720256, 67108864)
//   packed_info [16384, 2]    -> [67108864, 67141632)
//   ray_indices [8388608]     -> [67141632, 75530240)
//   mask        [8388608]     -> [75530240, 83918848)
// ----------------------------------------------------------------------------

#define N_RAYS     16384
#define MAX_STEPS  512
#define GRID_R     128
#define NEAR_F     0.05f
#define FAR_F      3.0f

static __device__ __forceinline__ float step_size() {
    // (3.0 - 0.05) / 512 in double, rounded once to float (matches jnp fp32 STEP)
    return (float)((3.0 - 0.05) / 512.0);
}

#define OFF_ORIG   0
#define OFF_DIR    25165824
#define OFF_S      50331648
#define OFF_E      58720256
#define OFF_PK     67108864
#define OFF_RI     67141632
#define OFF_MASK   75530240

__device__ int g_counts[N_RAYS];

__global__ void __launch_bounds__(MAX_STEPS)
sampler_kernel(const float* __restrict__ rays_o,
               const float* __restrict__ rays_d,
               const float* __restrict__ aabb,
               const int*   __restrict__ occ,     // bool as 4-byte: test != 0
               float* __restrict__ out)
{
    const int ray  = blockIdx.x;
    const int step = threadIdx.x;

    const float ox = rays_o[ray * 3 + 0];
    const float oy = rays_o[ray * 3 + 1];
    const float oz = rays_o[ray * 3 + 2];
    const float dx = rays_d[ray * 3 + 0];
    const float dy = rays_d[ray * 3 + 1];
    const float dz = rays_d[ray * 3 + 2];

    const float a0x = aabb[0], a0y = aabb[1], a0z = aabb[2];
    const float a1x = aabb[3], a1y = aabb[4], a1z = aabb[5];

    // --- ray/AABB intersection, separate rounding throughout ---
    const float sdx = (fabsf(dx) > 1e-10f) ? dx : 1e-10f;
    const float sdy = (fabsf(dy) > 1e-10f) ? dy : 1e-10f;
    const float sdz = (fabsf(dz) > 1e-10f) ? dz : 1e-10f;
    const float ix_ = __fdiv_rn(1.0f, sdx);
    const float iy_ = __fdiv_rn(1.0f, sdy);
    const float iz_ = __fdiv_rn(1.0f, sdz);

    const float t0x = __fmul_rn(__fsub_rn(a0x, ox), ix_);
    const float t1x = __fmul_rn(__fsub_rn(a1x, ox), ix_);
    const float t0y = __fmul_rn(__fsub_rn(a0y, oy), iy_);
    const float t1y = __fmul_rn(__fsub_rn(a1y, oy), iy_);
    const float t0z = __fmul_rn(__fsub_rn(a0z, oz), iz_);
    const float t1z = __fmul_rn(__fsub_rn(a1z, oz), iz_);

    const float tmin = fmaxf(fmaxf(fmaxf(fminf(t0x, t1x), fminf(t0y, t1y)),
                                   fminf(t0z, t1z)), NEAR_F);
    const float tmax = fminf(fminf(fminf(fmaxf(t0x, t1x), fmaxf(t0y, t1y)),
                                   fmaxf(t0z, t1z)), FAR_F);

    // --- segment geometry: NEAR + k*STEP with separate mul/add rounding ---
    const float STEPF = step_size();
    const float start = __fadd_rn(NEAR_F, __fmul_rn((float)step,       STEPF));
    const float end_  = __fadd_rn(NEAR_F, __fmul_rn((float)(step + 1), STEPF));
    const float mid   = __fmul_rn(0.5f, __fadd_rn(start, end_));

    // pos = o + d*mid, no FMA
    const float px = __fadd_rn(ox, __fmul_rn(dx, mid));
    const float py = __fadd_rn(oy, __fmul_rn(dy, mid));
    const float pz = __fadd_rn(oz, __fmul_rn(dz, mid));

    // scale = (pos - a0) / (a1 - a0)
    const float ex = __fsub_rn(a1x, a0x);
    const float ey = __fsub_rn(a1y, a0y);
    const float ez = __fsub_rn(a1z, a0z);
    const float sx = __fdiv_rn(__fsub_rn(px, a0x), ex);
    const float sy = __fdiv_rn(__fsub_rn(py, a0y), ey);
    const float sz = __fdiv_rn(__fsub_rn(pz, a0z), ez);

    const bool inside = (sx >= 0.0f) && (sx < 1.0f) &&
                        (sy >= 0.0f) && (sy < 1.0f) &&
                        (sz >= 0.0f) && (sz < 1.0f);

    // truncating cast matches astype(int32), then clip
    int gx = (int)__fmul_rn(sx, (float)GRID_R);
    int gy = (int)__fmul_rn(sy, (float)GRID_R);
    int gz = (int)__fmul_rn(sz, (float)GRID_R);
    gx = min(max(gx, 0), GRID_R - 1);
    gy = min(max(gy, 0), GRID_R - 1);
    gz = min(max(gz, 0), GRID_R - 1);

    const bool occv = (occ[(gx << 14) + (gy << 7) + gz] != 0);

    const bool valid = (start >= tmin) && (end_ <= tmax) && occv && inside;
    const float m = valid ? 1.0f : 0.0f;

    const int seg = (ray << 9) + step;

    out[OFF_ORIG + seg * 3 + 0] = __fmul_rn(ox, m);
    out[OFF_ORIG + seg * 3 + 1] = __fmul_rn(oy, m);
    out[OFF_ORIG + seg * 3 + 2] = __fmul_rn(oz, m);
    out[OFF_DIR  + seg * 3 + 0] = __fmul_rn(dx, m);
    out[OFF_DIR  + seg * 3 + 1] = __fmul_rn(dy, m);
    out[OFF_DIR  + seg * 3 + 2] = __fmul_rn(dz, m);
    out[OFF_S    + seg] = valid ? start : 0.0f;
    out[OFF_E    + seg] = valid ? end_  : 0.0f;
    out[OFF_RI   + seg] = (float)ray;
    out[OFF_MASK + seg] = m;

    // --- per-ray count via ballot + shared reduce ---
    const unsigned bal = __ballot_sync(0xFFFFFFFFu, valid);
    __shared__ int wsum[MAX_STEPS / 32];
    if ((threadIdx.x & 31) == 0)
        wsum[threadIdx.x >> 5] = __popc(bal);
    __syncthreads();
    if (threadIdx.x == 0) {
        int c = 0;
        #pragma unroll
        for (int i = 0; i < MAX_STEPS / 32; i++) c += wsum[i];
        g_counts[ray] = c;
    }
}

// Single-block exclusive scan over 16384 counts -> packed_info (offset, count).
__global__ void __launch_bounds__(1024)
scan_kernel(float* __restrict__ out)
{
    __shared__ int partial[1024];
    const int tid  = threadIdx.x;
    const int base = tid * 16;

    int local[16];
    int s = 0;
    #pragma unroll
    for (int i = 0; i < 16; i++) {
        local[i] = g_counts[base + i];
        s += local[i];
    }
    partial[tid] = s;
    __syncthreads();

    for (int off = 1; off < 1024; off <<= 1) {
        int v = (tid >= off) ? partial[tid - off] : 0;
        __syncthreads();
        partial[tid] += v;
        __syncthreads();
    }

    int excl = (tid == 0) ? 0 : partial[tid - 1];
    #pragma unroll
    for (int i = 0; i < 16; i++) {
        out[OFF_PK + 2 * (base + i) + 0] = (float)excl;
        out[OFF_PK + 2 * (base + i) + 1] = (float)local[i];
        excl += local[i];
    }
}

extern "C" void kernel_launch(void* const* d_in, const int* in_sizes, int n_in,
                              void* d_out, int out_size)
{
    const float* rays_o = (const float*)d_in[0];
    const float* rays_d = (const float*)d_in[1];
    const float* aabb   = (const float*)d_in[2];
    const int*   occ    = (const int*)  d_in[3];
    float* out = (float*)d_out;

    sampler_kernel<<<N_RAYS, MAX_STEPS>>>(rays_o, rays_d, aabb, occ, out);
    scan_kernel<<<1, 1024>>>(out);
}

// round 3
// speedup vs baseline: 1.2950x; 1.2950x over previous
#include <cuda_runtime.h>
#include <cuda_bf16.h>
#include <cstdint>

// ----------------------------------------------------------------------------
// VolumetricSampler: 16384 rays x 512 steps occupancy-grid sampling.
// Round 3: 4 steps/thread, all outputs written as STG.128; single-block
// vectorized scan. Predicate math uses __f*_rn (bit-exact vs JAX, proven R2).
//
// Output layout (all float32, concatenated reference outputs):
//   origins     [8388608, 3]  -> [0,        25165824)
//   dirs        [8388608, 3]  -> [25165824, 50331648)
//   s_flat      [8388608]     -> [50331648, 58720256)
//   e_flat      [8388608]     -> [58720256, 67108864)
//   packed_info [16384, 2]    -> [67108864, 67141632)
//   ray_indices [8388608]     -> [67141632, 75530240)
//   mask        [8388608]     -> [75530240, 83918848)
// ----------------------------------------------------------------------------

#define N_RAYS     16384
#define MAX_STEPS  512
#define GRID_R     128
#define NEAR_F     0.05f
#define FAR_F      3.0f

static __device__ __forceinline__ float step_size() {
    return (float)((3.0 - 0.05) / 512.0);   // fp32-rounded STEP, matches jnp
}

#define OFF_ORIG   0
#define OFF_DIR    25165824
#define OFF_S      50331648
#define OFF_E      58720256
#define OFF_PK     67108864
#define OFF_RI     67141632
#define OFF_MASK   75530240

__device__ __align__(16) int g_counts[N_RAYS];

// 256 threads/block, 2 rays/block, 128 threads/ray, 4 steps/thread.
__global__ void __launch_bounds__(256)
sampler_kernel(const float* __restrict__ rays_o,
               const float* __restrict__ rays_d,
               const float* __restrict__ aabb,
               const int*   __restrict__ occ,
               float* __restrict__ out)
{
    const int tid = threadIdx.x;
    const int ray = blockIdx.x * 2 + (tid >> 7);
    const int q   = tid & 127;          // quad index within ray
    const int s0  = q << 2;             // first step of this thread's quad

    const float ox = rays_o[ray * 3 + 0];
    const float oy = rays_o[ray * 3 + 1];
    const float oz = rays_o[ray * 3 + 2];
    const float dx = rays_d[ray * 3 + 0];
    const float dy = rays_d[ray * 3 + 1];
    const float dz = rays_d[ray * 3 + 2];

    const float a0x = aabb[0], a0y = aabb[1], a0z = aabb[2];
    const float a1x = aabb[3], a1y = aabb[4], a1z = aabb[5];

    // --- ray/AABB intersection (separate rounding) ---
    const float sdx = (fabsf(dx) > 1e-10f) ? dx : 1e-10f;
    const float sdy = (fabsf(dy) > 1e-10f) ? dy : 1e-10f;
    const float sdz = (fabsf(dz) > 1e-10f) ? dz : 1e-10f;
    const float ix_ = __fdiv_rn(1.0f, sdx);
    const float iy_ = __fdiv_rn(1.0f, sdy);
    const float iz_ = __fdiv_rn(1.0f, sdz);

    const float t0x = __fmul_rn(__fsub_rn(a0x, ox), ix_);
    const float t1x = __fmul_rn(__fsub_rn(a1x, ox), ix_);
    const float t0y = __fmul_rn(__fsub_rn(a0y, oy), iy_);
    const float t1y = __fmul_rn(__fsub_rn(a1y, oy), iy_);
    const float t0z = __fmul_rn(__fsub_rn(a0z, oz), iz_);
    const float t1z = __fmul_rn(__fsub_rn(a1z, oz), iz_);

    const float tmin = fmaxf(fmaxf(fmaxf(fminf(t0x, t1x), fminf(t0y, t1y)),
                                   fminf(t0z, t1z)), NEAR_F);
    const float tmax = fminf(fminf(fminf(fmaxf(t0x, t1x), fmaxf(t0y, t1y)),
                                   fmaxf(t0z, t1z)), FAR_F);

    const float ex = __fsub_rn(a1x, a0x);
    const float ey = __fsub_rn(a1y, a0y);
    const float ez = __fsub_rn(a1z, a0z);
    const float STEPF = step_size();

    float st[4], en[4], m[4];
    bool  valid[4];
    int   occ_idx[4];
    bool  pre[4];

    // Pass 1: geometry + predicates (occ indices computed; loads batched below)
    #pragma unroll
    for (int k = 0; k < 4; k++) {
        const int step = s0 + k;
        st[k] = __fadd_rn(NEAR_F, __fmul_rn((float)step,       STEPF));
        en[k] = __fadd_rn(NEAR_F, __fmul_rn((float)(step + 1), STEPF));
        const float mid = __fmul_rn(0.5f, __fadd_rn(st[k], en[k]));

        const float px = __fadd_rn(ox, __fmul_rn(dx, mid));
        const float py = __fadd_rn(oy, __fmul_rn(dy, mid));
        const float pz = __fadd_rn(oz, __fmul_rn(dz, mid));

        const float sx = __fdiv_rn(__fsub_rn(px, a0x), ex);
        const float sy = __fdiv_rn(__fsub_rn(py, a0y), ey);
        const float sz = __fdiv_rn(__fsub_rn(pz, a0z), ez);

        const bool inside = (sx >= 0.0f) && (sx < 1.0f) &&
                            (sy >= 0.0f) && (sy < 1.0f) &&
                            (sz >= 0.0f) && (sz < 1.0f);

        int gx = (int)__fmul_rn(sx, (float)GRID_R);
        int gy = (int)__fmul_rn(sy, (float)GRID_R);
        int gz = (int)__fmul_rn(sz, (float)GRID_R);
        gx = min(max(gx, 0), GRID_R - 1);
        gy = min(max(gy, 0), GRID_R - 1);
        gz = min(max(gz, 0), GRID_R - 1);

        occ_idx[k] = (gx << 14) + (gy << 7) + gz;
        pre[k] = (st[k] >= tmin) && (en[k] <= tmax) && inside;
    }

    // Pass 2: 4 independent occ loads (MLP), finalize valid/mask
    int ov[4];
    #pragma unroll
    for (int k = 0; k < 4; k++) ov[k] = occ[occ_idx[k]];
    int cnt = 0;
    #pragma unroll
    for (int k = 0; k < 4; k++) {
        valid[k] = pre[k] && (ov[k] != 0);
        m[k] = valid[k] ? 1.0f : 0.0f;
        cnt += valid[k] ? 1 : 0;
    }

    const int seg = (ray << 9) + s0;           // multiple of 4

    // --- vectorized stores ---
    const float rif = (float)ray;

    float4 sv = make_float4(valid[0] ? st[0] : 0.0f, valid[1] ? st[1] : 0.0f,
                            valid[2] ? st[2] : 0.0f, valid[3] ? st[3] : 0.0f);
    float4 ev = make_float4(valid[0] ? en[0] : 0.0f, valid[1] ? en[1] : 0.0f,
                            valid[2] ? en[2] : 0.0f, valid[3] ? en[3] : 0.0f);
    float4 rv = make_float4(rif, rif, rif, rif);
    float4 mv = make_float4(m[0], m[1], m[2], m[3]);

    *(float4*)(out + OFF_S    + seg) = sv;
    *(float4*)(out + OFF_E    + seg) = ev;
    *(float4*)(out + OFF_RI   + seg) = rv;
    *(float4*)(out + OFF_MASK + seg) = mv;

    // origins: 12 contiguous floats = 3 float4 (base is 16B aligned)
    const float omx0 = __fmul_rn(ox, m[0]), omy0 = __fmul_rn(oy, m[0]), omz0 = __fmul_rn(oz, m[0]);
    const float omx1 = __fmul_rn(ox, m[1]), omy1 = __fmul_rn(oy, m[1]), omz1 = __fmul_rn(oz, m[1]);
    const float omx2 = __fmul_rn(ox, m[2]), omy2 = __fmul_rn(oy, m[2]), omz2 = __fmul_rn(oz, m[2]);
    const float omx3 = __fmul_rn(ox, m[3]), omy3 = __fmul_rn(oy, m[3]), omz3 = __fmul_rn(oz, m[3]);
    float* ob = out + OFF_ORIG + seg * 3;
    *(float4*)(ob + 0) = make_float4(omx0, omy0, omz0, omx1);
    *(float4*)(ob + 4) = make_float4(omy1, omz1, omx2, omy2);
    *(float4*)(ob + 8) = make_float4(omz2, omx3, omy3, omz3);

    const float dmx0 = __fmul_rn(dx, m[0]), dmy0 = __fmul_rn(dy, m[0]), dmz0 = __fmul_rn(dz, m[0]);
    const float dmx1 = __fmul_rn(dx, m[1]), dmy1 = __fmul_rn(dy, m[1]), dmz1 = __fmul_rn(dz, m[1]);
    const float dmx2 = __fmul_rn(dx, m[2]), dmy2 = __fmul_rn(dy, m[2]), dmz2 = __fmul_rn(dz, m[2]);
    const float dmx3 = __fmul_rn(dx, m[3]), dmy3 = __fmul_rn(dy, m[3]), dmz3 = __fmul_rn(dz, m[3]);
    float* db = out + OFF_DIR + seg * 3;
    *(float4*)(db + 0) = make_float4(dmx0, dmy0, dmz0, dmx1);
    *(float4*)(db + 4) = make_float4(dmy1, dmz1, dmx2, dmy2);
    *(float4*)(db + 8) = make_float4(dmz2, dmx3, dmy3, dmz3);

    // --- per-ray count: warp reduce + smem combine (4 warps per ray) ---
    const int wsum = __reduce_add_sync(0xFFFFFFFFu, cnt);
    __shared__ int ws[8];
    if ((tid & 31) == 0) ws[tid >> 5] = wsum;
    __syncthreads();
    if (q == 0) {
        const int b = (tid >> 7) * 4;
        g_counts[ray] = ws[b] + ws[b + 1] + ws[b + 2] + ws[b + 3];
    }
}

// Single-block scan: 512 threads x 32 rays each. int4 loads, float4 stores.
__global__ void __launch_bounds__(512)
scan_kernel(float* __restrict__ out)
{
    const int tid = threadIdx.x;
    const int4* gc = (const int4*)g_counts;

    int c[32];
    int tot = 0;
    #pragma unroll
    for (int j = 0; j < 8; j++) {
        int4 v = gc[tid * 8 + j];
        c[j * 4 + 0] = v.x; c[j * 4 + 1] = v.y;
        c[j * 4 + 2] = v.z; c[j * 4 + 3] = v.w;
        tot += v.x + v.y + v.z + v.w;
    }

    __shared__ int sc[512];
    sc[tid] = tot;
    __syncthreads();

    // Hillis-Steele inclusive scan over 512 partials
    for (int off = 1; off < 512; off <<= 1) {
        int v = (tid >= off) ? sc[tid - off] : 0;
        __syncthreads();
        sc[tid] += v;
        __syncthreads();
    }

    int run = sc[tid] - tot;   // exclusive offset of this thread's first ray

    float4* pk = (float4*)(out + OFF_PK + tid * 64);   // 32 rays * 2 floats
    #pragma unroll
    for (int i = 0; i < 16; i++) {
        const int c0 = c[2 * i], c1 = c[2 * i + 1];
        pk[i] = make_float4((float)run, (float)c0,
                            (float)(run + c0), (float)c1);
        run += c0 + c1;
    }
}

extern "C" void kernel_launch(void* const* d_in, const int* in_sizes, int n_in,
                              void* d_out, int out_size)
{
    const float* rays_o = (const float*)d_in[0];
    const float* rays_d = (const float*)d_in[1];
    const float* aabb   = (const float*)d_in[2];
    const int*   occ    = (const int*)  d_in[3];
    float* out = (float*)d_out;

    sampler_kernel<<<N_RAYS / 2, 256>>>(rays_o, rays_d, aabb, occ, out);
    scan_kernel<<<1, 512>>>(out);
}